// round 1
// baseline (speedup 1.0000x reference)
#include <cuda_runtime.h>
#include <cstdint>

#define NE 8
#define DMODEL 1024
#define DFF 4096
#define TTOK 2048

#define BM 128
#define BN 64
#define BK 32
#define LDA 36   // 128-row A tile, padded: banks = 4*qr + qc, conflict-free
#define LDB 72   // 32-row B tile, padded: banks = 8*qc + qr, conflict-free

// Scratch (allocation-free rule: __device__ globals)
__device__ int   g_perm[TTOK];
__device__ int   g_off[NE + 1];
__device__ float g_h[(size_t)TTOK * DFF];   // gathered hidden activations

// ---------------- helpers ----------------
__device__ __forceinline__ void cp16(float* dst, const float* src, int sz) {
    uint32_t d = (uint32_t)__cvta_generic_to_shared(dst);
    asm volatile("cp.async.cg.shared.global [%0], [%1], 16, %2;\n"
                 :: "r"(d), "l"(src), "r"(sz));
}
__device__ __forceinline__ void cp_commit() {
    asm volatile("cp.async.commit_group;\n");
}
__device__ __forceinline__ uint32_t f2tf(float f) {
    uint32_t u;
    asm("cvt.rna.tf32.f32 %0, %1;\n" : "=r"(u) : "f"(f));
    return u;
}
__device__ __forceinline__ void mma8(float c[4], const uint32_t a[4], const uint32_t b[2]) {
    asm volatile(
        "mma.sync.aligned.m16n8k8.row.col.f32.tf32.tf32.f32 "
        "{%0,%1,%2,%3}, {%4,%5,%6,%7}, {%8,%9}, {%0,%1,%2,%3};\n"
        : "+f"(c[0]), "+f"(c[1]), "+f"(c[2]), "+f"(c[3])
        : "r"(a[0]), "r"(a[1]), "r"(a[2]), "r"(a[3]), "r"(b[0]), "r"(b[1]));
}

// ---------------- kernel 1: bucket tokens by expert ----------------
__global__ void moe_build_perm(const void* eidx_raw) {
    __shared__ int cnt[NE], base[NE], nz;
    int t = threadIdx.x;
    if (t < NE) cnt[t] = 0;
    if (t == 0) nz = 0;
    __syncthreads();

    // dtype detection: int64 data has all-zero high words; int32 random expert
    // ids at odd token positions are ~never all zero.
    const int* i32 = (const int*)eidx_raw;
    for (int i = t; i < TTOK / 2; i += blockDim.x)
        if (i32[2 * i + 1] != 0) atomicOr(&nz, 1);
    __syncthreads();
    bool is64 = (nz == 0);
    const long long* i64 = (const long long*)eidx_raw;

    for (int i = t; i < TTOK; i += blockDim.x) {
        int e = is64 ? (int)i64[i] : i32[i];
        atomicAdd(&cnt[e], 1);
    }
    __syncthreads();
    if (t == 0) {
        int s = 0;
        for (int e = 0; e < NE; e++) { g_off[e] = s; base[e] = s; s += cnt[e]; }
        g_off[NE] = s;
    }
    __syncthreads();
    for (int i = t; i < TTOK; i += blockDim.x) {
        int e = is64 ? (int)i64[i] : i32[i];
        int p = atomicAdd(&base[e], 1);
        g_perm[p] = i;
    }
}

// ---------------- kernel 2: gate+up GEMM + SwiGLU ----------------
// h[t, n] = silu(x@wg[e])[t,n] * (x@wu[e])[t,n], tokens gathered per expert
__global__ void __launch_bounds__(256)
moe_gateup(const float* __restrict__ x,
           const float* __restrict__ wg,
           const float* __restrict__ wu) {
    extern __shared__ float smem[];
    float* As = smem;                      // 2 * BM*LDA
    float* Bg = smem + 2 * BM * LDA;       // 2 * BK*LDB
    float* Bu = Bg + 2 * BK * LDB;         // 2 * BK*LDB

    const int e   = blockIdx.z;
    const int seg = g_off[e];
    const int cnt = g_off[e + 1] - seg;
    const int m0  = blockIdx.y * BM;
    if (m0 >= cnt) return;
    const int n0 = blockIdx.x * BN;

    const int tid = threadIdx.x;
    const int warp = tid >> 5, lane = tid & 31;
    const int wm = warp >> 1, wn = warp & 1;
    const int qr = lane >> 2, qc = lane & 3;

    const size_t wbase = (size_t)e * DMODEL * DFF + n0;
    const float* wgp = wg + wbase;
    const float* wup = wu + wbase;

    float cg[2][4][4], cu[2][4][4];
    #pragma unroll
    for (int i = 0; i < 2; i++)
        #pragma unroll
        for (int j = 0; j < 4; j++)
            #pragma unroll
            for (int k = 0; k < 4; k++) { cg[i][j][k] = 0.f; cu[i][j][k] = 0.f; }

    auto load_stage = [&](int buf, int k0) {
        float* as = As + buf * BM * LDA;
        float* bg = Bg + buf * BK * LDB;
        float* bu = Bu + buf * BK * LDB;
        #pragma unroll
        for (int i = 0; i < 4; i++) {              // A: 128 rows x 8 chunks
            int id = tid + i * 256;
            int r = id >> 3, c = (id & 7) * 4;
            int gm = m0 + r;
            const float* src = x;
            int sz = 0;
            if (gm < cnt) { src = x + (size_t)g_perm[seg + gm] * DMODEL + k0 + c; sz = 16; }
            cp16(as + r * LDA + c, src, sz);
        }
        #pragma unroll
        for (int i = 0; i < 2; i++) {              // B: 32 rows x 16 chunks, x2 mats
            int id = tid + i * 256;
            int r = id >> 4, c = (id & 15) * 4;
            size_t go = (size_t)(k0 + r) * DFF + c;
            cp16(bg + r * LDB + c, wgp + go, 16);
            cp16(bu + r * LDB + c, wup + go, 16);
        }
        cp_commit();
    };

    load_stage(0, 0);
    const int KT = DMODEL / BK;
    for (int kt = 0; kt < KT; ++kt) {
        if (kt + 1 < KT) {
            load_stage((kt + 1) & 1, (kt + 1) * BK);
            asm volatile("cp.async.wait_group 1;\n");
        } else {
            asm volatile("cp.async.wait_group 0;\n");
        }
        __syncthreads();
        const float* as  = As + (kt & 1) * BM * LDA;
        const float* bgs = Bg + (kt & 1) * BK * LDB;
        const float* bus = Bu + (kt & 1) * BK * LDB;
        #pragma unroll
        for (int ks = 0; ks < BK / 8; ++ks) {
            uint32_t a[2][4], fg[4][2], fu[4][2];
            #pragma unroll
            for (int mt = 0; mt < 2; mt++) {
                int r = wm * 32 + mt * 16 + qr;
                int c = ks * 8 + qc;
                a[mt][0] = f2tf(as[r * LDA + c]);
                a[mt][1] = f2tf(as[(r + 8) * LDA + c]);
                a[mt][2] = f2tf(as[r * LDA + c + 4]);
                a[mt][3] = f2tf(as[(r + 8) * LDA + c + 4]);
            }
            #pragma unroll
            for (int nt = 0; nt < 4; nt++) {
                int cc = wn * 32 + nt * 8 + qr;
                int rr = ks * 8 + qc;
                fg[nt][0] = f2tf(bgs[rr * LDB + cc]);
                fg[nt][1] = f2tf(bgs[(rr + 4) * LDB + cc]);
                fu[nt][0] = f2tf(bus[rr * LDB + cc]);
                fu[nt][1] = f2tf(bus[(rr + 4) * LDB + cc]);
            }
            #pragma unroll
            for (int mt = 0; mt < 2; mt++)
                #pragma unroll
                for (int nt = 0; nt < 4; nt++) {
                    mma8(cg[mt][nt], a[mt], fg[nt]);
                    mma8(cu[mt][nt], a[mt], fu[nt]);
                }
        }
        __syncthreads();
    }

    // epilogue: SwiGLU, write gathered hidden
    #pragma unroll
    for (int mt = 0; mt < 2; mt++)
        #pragma unroll
        for (int nt = 0; nt < 4; nt++)
            #pragma unroll
            for (int i = 0; i < 4; i++) {
                int row = wm * 32 + mt * 16 + qr + ((i >> 1) ? 8 : 0);
                int col = wn * 32 + nt * 8 + qc * 2 + (i & 1);
                int gm = m0 + row;
                if (gm < cnt) {
                    float g = cg[mt][nt][i], u = cu[mt][nt][i];
                    float h = u * (g / (1.f + __expf(-g)));
                    g_h[(size_t)(seg + gm) * DFF + n0 + col] = h;
                }
            }
}

// ---------------- kernel 3: down GEMM, scatter to output ----------------
__global__ void __launch_bounds__(256)
moe_down(const float* __restrict__ wd, float* __restrict__ out) {
    extern __shared__ float smem[];
    float* As = smem;                 // 2 * BM*LDA
    float* Bs = smem + 2 * BM * LDA;  // 2 * BK*LDB

    const int e   = blockIdx.z;
    const int seg = g_off[e];
    const int cnt = g_off[e + 1] - seg;
    const int m0  = blockIdx.y * BM;
    if (m0 >= cnt) return;
    const int n0 = blockIdx.x * BN;

    const int tid = threadIdx.x;
    const int warp = tid >> 5, lane = tid & 31;
    const int wm = warp >> 1, wn = warp & 1;
    const int qr = lane >> 2, qc = lane & 3;

    const float* wdp = wd + (size_t)e * DFF * DMODEL + n0;

    float acc[2][4][4];
    #pragma unroll
    for (int i = 0; i < 2; i++)
        #pragma unroll
        for (int j = 0; j < 4; j++)
            #pragma unroll
            for (int k = 0; k < 4; k++) acc[i][j][k] = 0.f;

    auto load_stage = [&](int buf, int k0) {
        float* as = As + buf * BM * LDA;
        float* bs = Bs + buf * BK * LDB;
        #pragma unroll
        for (int i = 0; i < 4; i++) {
            int id = tid + i * 256;
            int r = id >> 3, c = (id & 7) * 4;
            int gm = m0 + r;
            const float* src = g_h;
            int sz = 0;
            if (gm < cnt) { src = g_h + (size_t)(seg + gm) * DFF + k0 + c; sz = 16; }
            cp16(as + r * LDA + c, src, sz);
        }
        #pragma unroll
        for (int i = 0; i < 2; i++) {
            int id = tid + i * 256;
            int r = id >> 4, c = (id & 15) * 4;
            cp16(bs + r * LDB + c, wdp + (size_t)(k0 + r) * DMODEL + c, 16);
        }
        cp_commit();
    };

    load_stage(0, 0);
    const int KT = DFF / BK;
    for (int kt = 0; kt < KT; ++kt) {
        if (kt + 1 < KT) {
            load_stage((kt + 1) & 1, (kt + 1) * BK);
            asm volatile("cp.async.wait_group 1;\n");
        } else {
            asm volatile("cp.async.wait_group 0;\n");
        }
        __syncthreads();
        const float* as = As + (kt & 1) * BM * LDA;
        const float* bs = Bs + (kt & 1) * BK * LDB;
        #pragma unroll
        for (int ks = 0; ks < BK / 8; ++ks) {
            uint32_t a[2][4], fb[4][2];
            #pragma unroll
            for (int mt = 0; mt < 2; mt++) {
                int r = wm * 32 + mt * 16 + qr;
                int c = ks * 8 + qc;
                a[mt][0] = f2tf(as[r * LDA + c]);
                a[mt][1] = f2tf(as[(r + 8) * LDA + c]);
                a[mt][2] = f2tf(as[r * LDA + c + 4]);
                a[mt][3] = f2tf(as[(r + 8) * LDA + c + 4]);
            }
            #pragma unroll
            for (int nt = 0; nt < 4; nt++) {
                int cc = wn * 32 + nt * 8 + qr;
                int rr = ks * 8 + qc;
                fb[nt][0] = f2tf(bs[rr * LDB + cc]);
                fb[nt][1] = f2tf(bs[(rr + 4) * LDB + cc]);
            }
            #pragma unroll
            for (int mt = 0; mt < 2; mt++)
                #pragma unroll
                for (int nt = 0; nt < 4; nt++)
                    mma8(acc[mt][nt], a[mt], fb[nt]);
        }
        __syncthreads();
    }

    #pragma unroll
    for (int mt = 0; mt < 2; mt++)
        #pragma unroll
        for (int nt = 0; nt < 4; nt++)
            #pragma unroll
            for (int i = 0; i < 4; i++) {
                int row = wm * 32 + mt * 16 + qr + ((i >> 1) ? 8 : 0);
                int col = wn * 32 + nt * 8 + qc * 2 + (i & 1);
                int gm = m0 + row;
                if (gm < cnt)
                    out[(size_t)g_perm[seg + gm] * DMODEL + n0 + col] = acc[mt][nt][i];
            }
}

// ---------------- launch ----------------
extern "C" void kernel_launch(void* const* d_in, const int* in_sizes, int n_in,
                              void* d_out, int out_size) {
    const float* x  = (const float*)d_in[0];
    const void*  ei = d_in[1];
    const float* wg = (const float*)d_in[2];
    const float* wu = (const float*)d_in[3];
    const float* wd = (const float*)d_in[4];
    float* out = (float*)d_out;

    static_assert(2 * (BM * LDA + 2 * BK * LDB) * 4 == 73728, "smem1");
    cudaFuncSetAttribute(moe_gateup, cudaFuncAttributeMaxDynamicSharedMemorySize, 73728);
    cudaFuncSetAttribute(moe_down,   cudaFuncAttributeMaxDynamicSharedMemorySize, 55296);

    moe_build_perm<<<1, 256>>>(ei);

    dim3 g1(DFF / BN, TTOK / BM, NE);       // (64, 16, 8)
    moe_gateup<<<g1, 256, 73728>>>(x, wg, wu);

    dim3 g2(DMODEL / BN, TTOK / BM, NE);    // (16, 16, 8)
    moe_down<<<g2, 256, 55296>>>(wd, out);
}